// round 7
// baseline (speedup 1.0000x reference)
#include <cuda_runtime.h>

// Problem constants (fixed by the dataset):
//   x_in:    [N,1,H,W]   float32
//   filters: [N,81,H,W]  float32
//   bias:    [N,1,H,W]   float32
//   out:     [N,1,H,W]   float32
// out = sum_k patches(x)*filters + bias, 9x9 window, pad 4, dilation 1.

#define KSZ 9
#define PADR 4
#define NB 4
#define HH 544
#define WW 960
#define PLANE (HH * WW)          // 522240

#define TILE_W 128               // 32 threads * 4 outputs
#define TILE_H 8
#define SMEM_W (TILE_W + 2 * PADR)   // 136 floats per row (544B, 16B-aligned)
#define SMEM_H (TILE_H + 2 * PADR)   // 16 rows

// Allow up to 64 regs (4 CTAs/SM): keep the full 9x LDG.128 batch live so
// per-warp MLP ~ 9 and ptxas can pipeline next-row loads over current FMAs.
__global__ __launch_bounds__(256, 4)
void dfl_kernel(const float* __restrict__ x,
                const float* __restrict__ filt,
                const float* __restrict__ bias,
                float* __restrict__ out)
{
    __shared__ float sx[SMEM_H][SMEM_W];

    const int n  = blockIdx.z;
    const int bw = blockIdx.x * TILE_W;   // first output col of this tile
    const int bh = blockIdx.y * TILE_H;   // first output row of this tile
    const int tx = threadIdx.x;           // 0..31
    const int ty = threadIdx.y;           // 0..7
    const int tid = ty * 32 + tx;

    const float* __restrict__ xn = x + n * PLANE;

    // ---- cooperative load of x tile with halo (zero-padded) ----
    #pragma unroll
    for (int i = tid; i < SMEM_H * SMEM_W; i += 256) {
        const int r  = i / SMEM_W;
        const int c  = i - r * SMEM_W;
        const int gr = bh + r - PADR;
        const int gc = bw + c - PADR;
        float v = 0.0f;
        if ((unsigned)gr < (unsigned)HH && (unsigned)gc < (unsigned)WW)
            v = xn[gr * WW + gc];
        sx[r][c] = v;
    }
    __syncthreads();

    const int w = bw + tx * 4;            // first of 4 output cols
    const int h = bh + ty;                // output row (544 % 8 == 0, always valid)

    // 960 % 128 != 0: last block column is half-active. Guard AFTER the
    // barrier so every thread participated in the halo load above.
    if (w >= WW) return;                  // w < WW implies w+3 < WW

    const int pix = h * WW + w;
    const float4 b4 = *reinterpret_cast<const float4*>(bias + n * PLANE + pix);
    float a0 = b4.x, a1 = b4.y, a2 = b4.z, a3 = b4.w;

    const float* __restrict__ fbase = filt + (n * (KSZ * KSZ)) * PLANE + pix;

    #pragma unroll
    for (int dy = 0; dy < KSZ; ++dy) {
        // 12-wide x window for this row: local cols [tx*4 .. tx*4+11]
        const float4 t0 = *reinterpret_cast<const float4*>(&sx[ty + dy][tx * 4 + 0]);
        const float4 t1 = *reinterpret_cast<const float4*>(&sx[ty + dy][tx * 4 + 4]);
        const float4 t2 = *reinterpret_cast<const float4*>(&sx[ty + dy][tx * 4 + 8]);
        const float xv[12] = { t0.x, t0.y, t0.z, t0.w,
                               t1.x, t1.y, t1.z, t1.w,
                               t2.x, t2.y, t2.z, t2.w };

        // Full-row load batch: with a 64-reg budget all 9 float4 stay live
        // (MLP = 9 per warp) before the FMA drain.
        float4 f[KSZ];
        #pragma unroll
        for (int dx = 0; dx < KSZ; ++dx)
            f[dx] = *reinterpret_cast<const float4*>(fbase + (dy * KSZ + dx) * PLANE);

        #pragma unroll
        for (int dx = 0; dx < KSZ; ++dx) {
            a0 = fmaf(xv[dx + 0], f[dx].x, a0);
            a1 = fmaf(xv[dx + 1], f[dx].y, a1);
            a2 = fmaf(xv[dx + 2], f[dx].z, a2);
            a3 = fmaf(xv[dx + 3], f[dx].w, a3);
        }
    }

    *reinterpret_cast<float4*>(out + n * PLANE + pix) = make_float4(a0, a1, a2, a3);
}

extern "C" void kernel_launch(void* const* d_in, const int* in_sizes, int n_in,
                              void* d_out, int out_size)
{
    const float* x    = (const float*)d_in[0];   // x_in
    const float* filt = (const float*)d_in[1];   // filters
    const float* bias = (const float*)d_in[2];   // filters_biases
    float* out        = (float*)d_out;

    dim3 block(32, 8, 1);
    dim3 grid((WW + TILE_W - 1) / TILE_W,   // 8 (last block column half-active)
              HH / TILE_H,                  // 68
              NB);                          // 4
    dfl_kernel<<<grid, block>>>(x, filt, bias, out);
}

// round 8
// speedup vs baseline: 1.0973x; 1.0973x over previous
#include <cuda_runtime.h>

// Problem constants (fixed by the dataset):
//   x_in:    [N,1,H,W]   float32
//   filters: [N,81,H,W]  float32
//   bias:    [N,1,H,W]   float32
//   out:     [N,1,H,W]   float32
// out = sum_k patches(x)*filters + bias, 9x9 window, pad 4, dilation 1.

#define KSZ 9
#define PADR 4
#define NB 4
#define HH 544
#define WW 960
#define PLANE (HH * WW)          // 522240

#define TILE_W 128               // 32 threads * 4 outputs
#define TILE_H 8

// No shared memory, no barrier: x comes through L1/L2 (8.4 MB, L2-resident;
// ~9 KB/CTA, L1-resident). Filter LDG stream starts immediately at CTA launch.
__global__ __launch_bounds__(256)
void dfl_kernel(const float* __restrict__ x,
                const float* __restrict__ filt,
                const float* __restrict__ bias,
                float* __restrict__ out)
{
    const int n  = blockIdx.z;
    const int bw = blockIdx.x * TILE_W;
    const int bh = blockIdx.y * TILE_H;
    const int tx = threadIdx.x;           // 0..31
    const int ty = threadIdx.y;           // 0..7

    const int w = bw + tx * 4;            // first of 4 output cols
    const int h = bh + ty;                // output row (544 % 8 == 0)
    if (w >= WW) return;                  // last block column half-active

    const float* __restrict__ xn = x + n * PLANE;
    const int pix = h * WW + w;

    // Interior CTA: the 12-wide window [w-4, w+8) x rows [h-4, h+4] never
    // leaves the image for ANY thread of the block. Uniform per CTA.
    const bool interior = (bh >= PADR) && (bh + TILE_H + PADR <= HH) &&
                          (bw >= PADR) && (bw + TILE_W + PADR <= WW);

    const float4 b4 = __ldcs(reinterpret_cast<const float4*>(bias + n * PLANE + pix));
    float a0 = b4.x, a1 = b4.y, a2 = b4.z, a3 = b4.w;

    const float* __restrict__ fbase = filt + (n * (KSZ * KSZ)) * PLANE + pix;

    #pragma unroll
    for (int dy = 0; dy < KSZ; ++dy) {
        // 12-wide x window for this row: cols [w-4 .. w+7], all 16B-aligned.
        float xv[12];
        if (interior) {
            const float* xr = xn + (h + dy - PADR) * WW + (w - PADR);
            const float4 t0 = *reinterpret_cast<const float4*>(xr + 0);
            const float4 t1 = *reinterpret_cast<const float4*>(xr + 4);
            const float4 t2 = *reinterpret_cast<const float4*>(xr + 8);
            xv[0] = t0.x; xv[1]  = t0.y; xv[2]  = t0.z; xv[3]  = t0.w;
            xv[4] = t1.x; xv[5]  = t1.y; xv[6]  = t1.z; xv[7]  = t1.w;
            xv[8] = t2.x; xv[9]  = t2.y; xv[10] = t2.z; xv[11] = t2.w;
        } else {
            const int gr = h + dy - PADR;
            #pragma unroll
            for (int j = 0; j < 12; ++j) {
                const int gc = w - PADR + j;
                xv[j] = ((unsigned)gr < (unsigned)HH && (unsigned)gc < (unsigned)WW)
                            ? __ldg(xn + gr * WW + gc) : 0.0f;
            }
        }

        // Full-row filter batch: 9 independent streaming LDG.128 (MLP >= 9),
        // evict-first so filters never displace x in L2.
        float4 f[KSZ];
        #pragma unroll
        for (int dx = 0; dx < KSZ; ++dx)
            f[dx] = __ldcs(reinterpret_cast<const float4*>(fbase + (dy * KSZ + dx) * PLANE));

        #pragma unroll
        for (int dx = 0; dx < KSZ; ++dx) {
            a0 = fmaf(xv[dx + 0], f[dx].x, a0);
            a1 = fmaf(xv[dx + 1], f[dx].y, a1);
            a2 = fmaf(xv[dx + 2], f[dx].z, a2);
            a3 = fmaf(xv[dx + 3], f[dx].w, a3);
        }
    }

    __stcs(reinterpret_cast<float4*>(out + n * PLANE + pix),
           make_float4(a0, a1, a2, a3));
}

extern "C" void kernel_launch(void* const* d_in, const int* in_sizes, int n_in,
                              void* d_out, int out_size)
{
    const float* x    = (const float*)d_in[0];   // x_in
    const float* filt = (const float*)d_in[1];   // filters
    const float* bias = (const float*)d_in[2];   // filters_biases
    float* out        = (float*)d_out;

    dim3 block(32, 8, 1);
    dim3 grid((WW + TILE_W - 1) / TILE_W,   // 8 (last block column half-active)
              HH / TILE_H,                  // 68
              NB);                          // 4
    dfl_kernel<<<grid, block>>>(x, filt, bias, out);
}